// round 1
// baseline (speedup 1.0000x reference)
#include <cuda_runtime.h>
#include <math.h>

// Problem constants
#define BB 4
#define SS 2048
#define DD 1024
#define HH 16
#define HD 64
#define MROWS (BB * SS)   // 8192

// Scratch (allocation-free: __device__ globals)
__device__ float g_K[BB * HH * SS * HD];
__device__ float g_Q[BB * HH * SS * HD];
__device__ float g_V[BB * HH * SS * HD];
__device__ float g_Y[BB * SS * DD];

// ---------------------------------------------------------------------------
// GEMM 1: kqv = x @ W_attn^T + b_attn, scattered into K/Q/V [B,H,S,HD]
// C[m,n] = sum_k A[m,k] * W[n,k]; M=8192, N=3072, K=1024
// Tiles 128x128x16, 256 threads, 8x8 micro-tile per thread.
// ---------------------------------------------------------------------------
__global__ __launch_bounds__(256) void gemm_qkv_kernel(
    const float* __restrict__ A, const float* __restrict__ W,
    const float* __restrict__ bias)
{
    __shared__ float As[16][128];
    __shared__ float Bs[16][128];
    const int t = threadIdx.x;
    const int tx = t & 15, ty = t >> 4;
    const int mBase = blockIdx.y * 128;
    const int nBase = blockIdx.x * 128;
    const int KD = 1024;

    float acc[8][8];
#pragma unroll
    for (int i = 0; i < 8; i++)
#pragma unroll
        for (int j = 0; j < 8; j++) acc[i][j] = 0.f;

    for (int k0 = 0; k0 < KD; k0 += 16) {
#pragma unroll
        for (int u0 = 0; u0 < 2; u0++) {
            int u = t + u0 * 256;      // 0..511
            int row = u >> 2, cg = u & 3;
            float4 va = *(const float4*)&A[(size_t)(mBase + row) * KD + k0 + cg * 4];
            As[cg * 4 + 0][row] = va.x; As[cg * 4 + 1][row] = va.y;
            As[cg * 4 + 2][row] = va.z; As[cg * 4 + 3][row] = va.w;
            float4 vb = *(const float4*)&W[(size_t)(nBase + row) * KD + k0 + cg * 4];
            Bs[cg * 4 + 0][row] = vb.x; Bs[cg * 4 + 1][row] = vb.y;
            Bs[cg * 4 + 2][row] = vb.z; Bs[cg * 4 + 3][row] = vb.w;
        }
        __syncthreads();
#pragma unroll
        for (int kk = 0; kk < 16; kk++) {
            float a[8], b[8];
            *(float4*)&a[0] = *(const float4*)&As[kk][ty * 8];
            *(float4*)&a[4] = *(const float4*)&As[kk][ty * 8 + 4];
            *(float4*)&b[0] = *(const float4*)&Bs[kk][tx * 8];
            *(float4*)&b[4] = *(const float4*)&Bs[kk][tx * 8 + 4];
#pragma unroll
            for (int i = 0; i < 8; i++)
#pragma unroll
                for (int j = 0; j < 8; j++)
                    acc[i][j] += a[i] * b[j];
        }
        __syncthreads();
    }

    // Epilogue: add bias, scatter into K/Q/V [B,H,S,HD]  (split order: k, q, v)
#pragma unroll
    for (int i = 0; i < 8; i++) {
        int m = mBase + ty * 8 + i;
        int b = m >> 11;          // / 2048
        int s = m & 2047;
#pragma unroll
        for (int j = 0; j < 8; j++) {
            int n = nBase + tx * 8 + j;
            float v = acc[i][j] + bias[n];
            int chunk = n >> 10;  // 0=k, 1=q, 2=v
            int d = n & 1023;
            int h = d >> 6;
            int hd = d & 63;
            size_t idx = ((size_t)(b * HH + h) * SS + s) * HD + hd;
            if (chunk == 0)      g_K[idx] = v;
            else if (chunk == 1) g_Q[idx] = v;
            else                 g_V[idx] = v;
        }
    }
}

// ---------------------------------------------------------------------------
// GEMM 2: out = Y @ W_out^T + b_out; M=8192, N=1024, K=1024
// ---------------------------------------------------------------------------
__global__ __launch_bounds__(256) void gemm_out_kernel(
    const float* __restrict__ W, const float* __restrict__ bias,
    float* __restrict__ out)
{
    __shared__ float As[16][128];
    __shared__ float Bs[16][128];
    const int t = threadIdx.x;
    const int tx = t & 15, ty = t >> 4;
    const int mBase = blockIdx.y * 128;
    const int nBase = blockIdx.x * 128;
    const int KD = 1024;

    float acc[8][8];
#pragma unroll
    for (int i = 0; i < 8; i++)
#pragma unroll
        for (int j = 0; j < 8; j++) acc[i][j] = 0.f;

    for (int k0 = 0; k0 < KD; k0 += 16) {
#pragma unroll
        for (int u0 = 0; u0 < 2; u0++) {
            int u = t + u0 * 256;
            int row = u >> 2, cg = u & 3;
            float4 va = *(const float4*)&g_Y[(size_t)(mBase + row) * KD + k0 + cg * 4];
            As[cg * 4 + 0][row] = va.x; As[cg * 4 + 1][row] = va.y;
            As[cg * 4 + 2][row] = va.z; As[cg * 4 + 3][row] = va.w;
            float4 vb = *(const float4*)&W[(size_t)(nBase + row) * KD + k0 + cg * 4];
            Bs[cg * 4 + 0][row] = vb.x; Bs[cg * 4 + 1][row] = vb.y;
            Bs[cg * 4 + 2][row] = vb.z; Bs[cg * 4 + 3][row] = vb.w;
        }
        __syncthreads();
#pragma unroll
        for (int kk = 0; kk < 16; kk++) {
            float a[8], b[8];
            *(float4*)&a[0] = *(const float4*)&As[kk][ty * 8];
            *(float4*)&a[4] = *(const float4*)&As[kk][ty * 8 + 4];
            *(float4*)&b[0] = *(const float4*)&Bs[kk][tx * 8];
            *(float4*)&b[4] = *(const float4*)&Bs[kk][tx * 8 + 4];
#pragma unroll
            for (int i = 0; i < 8; i++)
#pragma unroll
                for (int j = 0; j < 8; j++)
                    acc[i][j] += a[i] * b[j];
        }
        __syncthreads();
    }

#pragma unroll
    for (int i = 0; i < 8; i++) {
        int m = mBase + ty * 8 + i;
#pragma unroll
        for (int j = 0; j < 8; j += 4) {
            int n = nBase + tx * 8 + j;
            float4 o;
            o.x = acc[i][j + 0] + bias[n + 0];
            o.y = acc[i][j + 1] + bias[n + 1];
            o.z = acc[i][j + 2] + bias[n + 2];
            o.w = acc[i][j + 3] + bias[n + 3];
            *(float4*)&out[(size_t)m * 1024 + n] = o;
        }
    }
}

// ---------------------------------------------------------------------------
// Flash-attention style kernel. One CTA per (b*H+h, 64-row q-block).
// 256 threads; 4x4 micro-tiles; all smem tiles stride 68 (float4-aligned,
// conflict-free LDS.128 access patterns). Online softmax over 32 key tiles.
// Writes output directly in [B,S,D] layout (pre-permuted for out GEMM).
// ---------------------------------------------------------------------------
#define SP 68

__global__ __launch_bounds__(256) void attn_kernel()
{
    extern __shared__ float sm[];
    float* Qs = sm;                // [d][m]
    float* Ks = sm + 64 * SP;      // [d][k]
    float* Vs = sm + 2 * 64 * SP;  // [k][c]
    float* Ps = sm + 3 * 64 * SP;  // [k][m]

    const int t = threadIdx.x;
    const int tc = t & 15, tr = t >> 4;
    const int mt = tr * 4, ct = tc * 4;
    const int bh = blockIdx.x;      // 0..63
    const int mblk = blockIdx.y;    // 0..31

    const float* Qg = g_Q + ((size_t)bh * SS + mblk * 64) * HD;
    const float* Kg0 = g_K + (size_t)bh * SS * HD;
    const float* Vg0 = g_V + (size_t)bh * SS * HD;

    // Load Q tile transposed: global [m][d] -> Qs[d][m]
#pragma unroll
    for (int u0 = 0; u0 < 4; u0++) {
        int u = t + u0 * 256;       // 0..1023
        int row = u >> 4, cg = u & 15;
        float4 v = *(const float4*)&Qg[row * 64 + cg * 4];
        Qs[(cg * 4 + 0) * SP + row] = v.x;
        Qs[(cg * 4 + 1) * SP + row] = v.y;
        Qs[(cg * 4 + 2) * SP + row] = v.z;
        Qs[(cg * 4 + 3) * SP + row] = v.w;
    }

    float acc[4][4];
    float mi[4], li[4];
#pragma unroll
    for (int i = 0; i < 4; i++) {
        mi[i] = -1e30f; li[i] = 0.f;
#pragma unroll
        for (int j = 0; j < 4; j++) acc[i][j] = 0.f;
    }

    for (int jt = 0; jt < SS / 64; jt++) {
        __syncthreads();  // everyone done with previous Ks/Vs/Ps (and Qs ready on iter 0)
        const float* Kg = Kg0 + jt * 64 * HD;
        const float* Vg = Vg0 + jt * 64 * HD;
#pragma unroll
        for (int u0 = 0; u0 < 4; u0++) {
            int u = t + u0 * 256;
            int row = u >> 4, cg = u & 15;
            float4 vk = *(const float4*)&Kg[row * 64 + cg * 4];
            Ks[(cg * 4 + 0) * SP + row] = vk.x;
            Ks[(cg * 4 + 1) * SP + row] = vk.y;
            Ks[(cg * 4 + 2) * SP + row] = vk.z;
            Ks[(cg * 4 + 3) * SP + row] = vk.w;
            float4 vv = *(const float4*)&Vg[row * 64 + cg * 4];
            *(float4*)&Vs[row * SP + cg * 4] = vv;
        }
        __syncthreads();

        // Scores: S[mt..mt+3][ct..ct+3] = Q(64xHD) . K^T
        float s[4][4];
#pragma unroll
        for (int i = 0; i < 4; i++)
#pragma unroll
            for (int j = 0; j < 4; j++) s[i][j] = 0.f;
#pragma unroll 16
        for (int d = 0; d < 64; d++) {
            float4 q4 = *(const float4*)&Qs[d * SP + mt];
            float4 k4 = *(const float4*)&Ks[d * SP + ct];
            float qa[4] = {q4.x, q4.y, q4.z, q4.w};
            float ka[4] = {k4.x, k4.y, k4.z, k4.w};
#pragma unroll
            for (int i = 0; i < 4; i++)
#pragma unroll
                for (int j = 0; j < 4; j++)
                    s[i][j] += qa[i] * ka[j];
        }
#pragma unroll
        for (int i = 0; i < 4; i++)
#pragma unroll
            for (int j = 0; j < 4; j++) s[i][j] *= 0.125f;  // 1/sqrt(64)

        // Row max across the 16 threads of this row group (consecutive lanes)
        float rmax[4], rsum[4];
#pragma unroll
        for (int i = 0; i < 4; i++)
            rmax[i] = fmaxf(fmaxf(s[i][0], s[i][1]), fmaxf(s[i][2], s[i][3]));
#pragma unroll
        for (int off = 1; off < 16; off <<= 1)
#pragma unroll
            for (int i = 0; i < 4; i++)
                rmax[i] = fmaxf(rmax[i], __shfl_xor_sync(0xffffffffu, rmax[i], off));

#pragma unroll
        for (int i = 0; i < 4; i++) {
            float mnew = fmaxf(mi[i], rmax[i]);
            float corr = __expf(mi[i] - mnew);
            mi[i] = mnew;
            li[i] *= corr;
#pragma unroll
            for (int j = 0; j < 4; j++) acc[i][j] *= corr;
            rsum[i] = 0.f;
#pragma unroll
            for (int j = 0; j < 4; j++) {
                s[i][j] = __expf(s[i][j] - mnew);
                rsum[i] += s[i][j];
            }
        }
#pragma unroll
        for (int off = 1; off < 16; off <<= 1)
#pragma unroll
            for (int i = 0; i < 4; i++)
                rsum[i] += __shfl_xor_sync(0xffffffffu, rsum[i], off);
#pragma unroll
        for (int i = 0; i < 4; i++) li[i] += rsum[i];

        // Write P transposed: Ps[k][m]
#pragma unroll
        for (int j = 0; j < 4; j++) {
            float4 pv = make_float4(s[0][j], s[1][j], s[2][j], s[3][j]);
            *(float4*)&Ps[(ct + j) * SP + mt] = pv;
        }
        __syncthreads();

        // O += P @ V
#pragma unroll 16
        for (int k = 0; k < 64; k++) {
            float4 p4 = *(const float4*)&Ps[k * SP + mt];
            float4 v4 = *(const float4*)&Vs[k * SP + ct];
            float pa[4] = {p4.x, p4.y, p4.z, p4.w};
            float va[4] = {v4.x, v4.y, v4.z, v4.w};
#pragma unroll
            for (int i = 0; i < 4; i++)
#pragma unroll
                for (int j = 0; j < 4; j++)
                    acc[i][j] += pa[i] * va[j];
        }
    }

    // Output: normalize and write to Y in [B,S,D] layout
    const int b = bh >> 4, h = bh & 15;
    float* Yb = g_Y + ((size_t)b * SS + mblk * 64) * DD + h * HD;
#pragma unroll
    for (int i = 0; i < 4; i++) {
        float inv = 1.f / li[i];
        float4 o = make_float4(acc[i][0] * inv, acc[i][1] * inv,
                               acc[i][2] * inv, acc[i][3] * inv);
        *(float4*)&Yb[(size_t)(mt + i) * DD + ct] = o;
    }
}

// ---------------------------------------------------------------------------
extern "C" void kernel_launch(void* const* d_in, const int* in_sizes, int n_in,
                              void* d_out, int out_size)
{
    const float* x      = (const float*)d_in[0];   // [4,2048,1024]
    const float* W_attn = (const float*)d_in[1];   // [3072,1024]
    const float* b_attn = (const float*)d_in[2];   // [3072]
    const float* W_out  = (const float*)d_in[3];   // [1024,1024]
    const float* b_out  = (const float*)d_in[4];   // [1024]
    float* out = (float*)d_out;                    // [4,2048,1024]

    (void)in_sizes; (void)n_in; (void)out_size;

    dim3 thr(256);

    // 1) QKV projection + scatter to [B,H,S,HD]
    gemm_qkv_kernel<<<dim3(3072 / 128, MROWS / 128), thr>>>(x, W_attn, b_attn);

    // 2) Attention (flash-style), writes Y in [B,S,D]
    size_t smem = (size_t)4 * 64 * SP * sizeof(float);  // 69632 B
    cudaFuncSetAttribute((const void*)attn_kernel,
                         cudaFuncAttributeMaxDynamicSharedMemorySize, (int)smem);
    attn_kernel<<<dim3(BB * HH, SS / 64), thr, smem>>>();

    // 3) Output projection
    gemm_out_kernel<<<dim3(1024 / 128, MROWS / 128), thr>>>(W_out, b_out, out);
}

// round 2
// speedup vs baseline: 2.2638x; 2.2638x over previous
#include <cuda_runtime.h>
#include <math.h>

#define BB 4
#define SS 2048
#define DD 1024
#define HH 16
#define HD 64
#define MROWS (BB * SS)   // 8192

// Scratch (allocation-free: __device__ globals)
__device__ float g_K[BB * HH * SS * HD];
__device__ float g_Q[BB * HH * SS * HD];
__device__ float g_V[BB * HH * SS * HD];
__device__ float g_Y[BB * SS * DD];

// ---------------------------------------------------------------------------
// TF32 helpers
// ---------------------------------------------------------------------------
__device__ __forceinline__ unsigned f2t(float f) {
    unsigned u;
    asm("cvt.rna.tf32.f32 %0, %1;" : "=r"(u) : "f"(f));
    return u;
}

__device__ __forceinline__ void mma8(float* c, const unsigned* a, const unsigned* b) {
    asm volatile(
        "mma.sync.aligned.m16n8k8.row.col.f32.tf32.tf32.f32 "
        "{%0,%1,%2,%3}, {%4,%5,%6,%7}, {%8,%9}, {%0,%1,%2,%3};\n"
        : "+f"(c[0]), "+f"(c[1]), "+f"(c[2]), "+f"(c[3])
        : "r"(a[0]), "r"(a[1]), "r"(a[2]), "r"(a[3]), "r"(b[0]), "r"(b[1]));
}

// ---------------------------------------------------------------------------
// TF32 tensor-core GEMM: C[m,n] = sum_k A[m,k]*W[n,k] + bias[n]
// BLK 128x128x32, 256 threads (8 warps: 4 m x 2 n), warp tile 32x64.
// EPI==0: A from param, scatter into g_K/g_Q/g_V (split order k,q,v)
// EPI==1: A = g_Y (device global), plain store to out
// ---------------------------------------------------------------------------
template <int EPI>
__global__ __launch_bounds__(256) void gemm_tc(
    const float* __restrict__ Ap, const float* __restrict__ W,
    const float* __restrict__ bias, float* __restrict__ out)
{
    const float* A = (EPI == 0) ? Ap : (const float*)g_Y;
    __shared__ unsigned As[128 * 36];
    __shared__ unsigned Bs[128 * 36];
    const int t = threadIdx.x, lane = t & 31, warp = t >> 5;
    const int wm = warp & 3, wn = warp >> 2;
    const int r = lane >> 2, c = lane & 3;
    const int mBase = blockIdx.y * 128, nBase = blockIdx.x * 128;
    const int KD = 1024;

    float acc[2][8][4];
#pragma unroll
    for (int i = 0; i < 2; i++)
#pragma unroll
        for (int j = 0; j < 8; j++)
#pragma unroll
            for (int q = 0; q < 4; q++) acc[i][j][q] = 0.f;

    for (int k0 = 0; k0 < KD; k0 += 32) {
#pragma unroll
        for (int u0 = 0; u0 < 4; u0++) {
            int u = t + u0 * 256;
            int row = u >> 3, cg = u & 7;
            float4 va = *(const float4*)&A[(size_t)(mBase + row) * KD + k0 + cg * 4];
            *(uint4*)&As[row * 36 + cg * 4] =
                make_uint4(f2t(va.x), f2t(va.y), f2t(va.z), f2t(va.w));
            float4 vb = *(const float4*)&W[(size_t)(nBase + row) * KD + k0 + cg * 4];
            *(uint4*)&Bs[row * 36 + cg * 4] =
                make_uint4(f2t(vb.x), f2t(vb.y), f2t(vb.z), f2t(vb.w));
        }
        __syncthreads();

#pragma unroll
        for (int kk = 0; kk < 4; kk++) {
            unsigned a[2][4], b[8][2];
#pragma unroll
            for (int i = 0; i < 2; i++) {
                int m0 = wm * 32 + i * 16;
                a[i][0] = As[(m0 + r) * 36 + kk * 8 + c];
                a[i][1] = As[(m0 + r + 8) * 36 + kk * 8 + c];
                a[i][2] = As[(m0 + r) * 36 + kk * 8 + c + 4];
                a[i][3] = As[(m0 + r + 8) * 36 + kk * 8 + c + 4];
            }
#pragma unroll
            for (int j = 0; j < 8; j++) {
                int n0 = wn * 64 + j * 8 + r;
                b[j][0] = Bs[n0 * 36 + kk * 8 + c];
                b[j][1] = Bs[n0 * 36 + kk * 8 + c + 4];
            }
#pragma unroll
            for (int i = 0; i < 2; i++)
#pragma unroll
                for (int j = 0; j < 8; j++)
                    mma8(acc[i][j], a[i], b[j]);
        }
        __syncthreads();
    }

#pragma unroll
    for (int i = 0; i < 2; i++) {
#pragma unroll
        for (int j = 0; j < 8; j++) {
            int mg0 = mBase + wm * 32 + i * 16 + r;
            int ng = nBase + wn * 64 + j * 8 + 2 * c;
            if (EPI == 0) {
#pragma unroll
                for (int h = 0; h < 2; h++) {
                    int m = mg0 + h * 8;
                    int bb = m >> 11, s = m & 2047;
#pragma unroll
                    for (int e = 0; e < 2; e++) {
                        int n = ng + e;
                        float v = acc[i][j][h * 2 + e] + bias[n];
                        int chunk = n >> 10;
                        int d = n & 1023;
                        int hh = d >> 6, hd = d & 63;
                        size_t idx = ((size_t)(bb * HH + hh) * SS + s) * HD + hd;
                        if (chunk == 0)      g_K[idx] = v;
                        else if (chunk == 1) g_Q[idx] = v;
                        else                 g_V[idx] = v;
                    }
                }
            } else {
                float2 bv = *(const float2*)&bias[ng];
                *(float2*)&out[(size_t)mg0 * DD + ng] =
                    make_float2(acc[i][j][0] + bv.x, acc[i][j][1] + bv.y);
                *(float2*)&out[(size_t)(mg0 + 8) * DD + ng] =
                    make_float2(acc[i][j][2] + bv.x, acc[i][j][3] + bv.y);
            }
        }
    }
}

// ---------------------------------------------------------------------------
// Flash attention with TF32 tensor cores (see header comment in analysis).
// ---------------------------------------------------------------------------
#define AST 68
#define VST 72

__global__ __launch_bounds__(256) void attn_tc()
{
    extern __shared__ unsigned smx[];
    unsigned* Qs = smx;                    // [64][AST] (m,d)
    unsigned* Ks = smx + 64 * AST;         // [64][AST] (n,d)
    unsigned* Su = smx + 2 * 64 * AST;     // [64][AST] scores(float)/P(tf32)
    unsigned* Vs = smx + 3 * 64 * AST;     // [64][VST] (k,n)
    float* Sf = (float*)Su;
    float* row_m = (float*)(smx + 3 * 64 * AST + 64 * VST);
    float* row_l = row_m + 64;
    float* corr_s = row_l + 64;

    const int t = threadIdx.x, lane = t & 31, warp = t >> 5;
    const int wm = warp & 1, wn = warp >> 1;
    const int r = lane >> 2, c = lane & 3;
    const int bh = blockIdx.x, mblk = blockIdx.y;

    const float* Qg = g_Q + ((size_t)bh * SS + mblk * 64) * HD;
    const float* Kg0 = g_K + (size_t)bh * SS * HD;
    const float* Vg0 = g_V + (size_t)bh * SS * HD;

#pragma unroll
    for (int u0 = 0; u0 < 4; u0++) {
        int u = t + u0 * 256;
        int row = u >> 4, cg = u & 15;
        float4 v = *(const float4*)&Qg[row * 64 + cg * 4];
        *(uint4*)&Qs[row * AST + cg * 4] =
            make_uint4(f2t(v.x), f2t(v.y), f2t(v.z), f2t(v.w));
    }
    if (t < 64) { row_m[t] = -1e30f; row_l[t] = 0.f; }

    float oacc[2][2][4];
#pragma unroll
    for (int i = 0; i < 2; i++)
#pragma unroll
        for (int j = 0; j < 2; j++)
#pragma unroll
            for (int q = 0; q < 4; q++) oacc[i][j][q] = 0.f;

    for (int jt = 0; jt < SS / 64; jt++) {
        __syncthreads();
        const float* Kg = Kg0 + jt * 64 * HD;
        const float* Vg = Vg0 + jt * 64 * HD;
#pragma unroll
        for (int u0 = 0; u0 < 4; u0++) {
            int u = t + u0 * 256;
            int row = u >> 4, cg = u & 15;
            float4 vk = *(const float4*)&Kg[row * 64 + cg * 4];
            *(uint4*)&Ks[row * AST + cg * 4] =
                make_uint4(f2t(vk.x), f2t(vk.y), f2t(vk.z), f2t(vk.w));
            float4 vv = *(const float4*)&Vg[row * 64 + cg * 4];
            *(uint4*)&Vs[row * VST + cg * 4] =
                make_uint4(f2t(vv.x), f2t(vv.y), f2t(vv.z), f2t(vv.w));
        }
        __syncthreads();

        float sacc[2][2][4];
#pragma unroll
        for (int i = 0; i < 2; i++)
#pragma unroll
            for (int j = 0; j < 2; j++)
#pragma unroll
                for (int q = 0; q < 4; q++) sacc[i][j][q] = 0.f;

#pragma unroll
        for (int kk = 0; kk < 8; kk++) {
            unsigned a[2][4], b[2][2];
#pragma unroll
            for (int i = 0; i < 2; i++) {
                int m0 = wm * 32 + i * 16;
                a[i][0] = Qs[(m0 + r) * AST + kk * 8 + c];
                a[i][1] = Qs[(m0 + r + 8) * AST + kk * 8 + c];
                a[i][2] = Qs[(m0 + r) * AST + kk * 8 + c + 4];
                a[i][3] = Qs[(m0 + r + 8) * AST + kk * 8 + c + 4];
            }
#pragma unroll
            for (int j = 0; j < 2; j++) {
                int n0 = wn * 16 + j * 8 + r;
                b[j][0] = Ks[n0 * AST + kk * 8 + c];
                b[j][1] = Ks[n0 * AST + kk * 8 + c + 4];
            }
#pragma unroll
            for (int i = 0; i < 2; i++)
#pragma unroll
                for (int j = 0; j < 2; j++)
                    mma8(sacc[i][j], a[i], b[j]);
        }

#pragma unroll
        for (int i = 0; i < 2; i++)
#pragma unroll
            for (int j = 0; j < 2; j++) {
                int m0 = wm * 32 + i * 16 + r;
                int n0 = wn * 16 + j * 8 + 2 * c;
                *(float2*)&Sf[m0 * AST + n0] =
                    make_float2(sacc[i][j][0] * 0.125f, sacc[i][j][1] * 0.125f);
                *(float2*)&Sf[(m0 + 8) * AST + n0] =
                    make_float2(sacc[i][j][2] * 0.125f, sacc[i][j][3] * 0.125f);
            }
        __syncthreads();

        {
            int row = t >> 2, q = t & 3;
            float v[16];
#pragma unroll
            for (int ii = 0; ii < 4; ii++) {
                float4 f = *(const float4*)&Sf[row * AST + q * 16 + ii * 4];
                v[ii * 4 + 0] = f.x; v[ii * 4 + 1] = f.y;
                v[ii * 4 + 2] = f.z; v[ii * 4 + 3] = f.w;
            }
            float mx = v[0];
#pragma unroll
            for (int e = 1; e < 16; e++) mx = fmaxf(mx, v[e]);
            mx = fmaxf(mx, __shfl_xor_sync(0xffffffffu, mx, 1));
            mx = fmaxf(mx, __shfl_xor_sync(0xffffffffu, mx, 2));
            float old = row_m[row];
            float mnew = fmaxf(old, mx);
            float corr = __expf(old - mnew);
            float sum = 0.f;
            unsigned pv[16];
#pragma unroll
            for (int e = 0; e < 16; e++) {
                float p = __expf(v[e] - mnew);
                sum += p;
                pv[e] = f2t(p);
            }
            sum += __shfl_xor_sync(0xffffffffu, sum, 1);
            sum += __shfl_xor_sync(0xffffffffu, sum, 2);
#pragma unroll
            for (int ii = 0; ii < 4; ii++)
                *(uint4*)&Su[row * AST + q * 16 + ii * 4] =
                    make_uint4(pv[ii * 4], pv[ii * 4 + 1], pv[ii * 4 + 2], pv[ii * 4 + 3]);
            if (q == 0) {
                row_m[row] = mnew;
                row_l[row] = row_l[row] * corr + sum;
                corr_s[row] = corr;
            }
        }
        __syncthreads();

#pragma unroll
        for (int i = 0; i < 2; i++) {
            int m0 = wm * 32 + i * 16 + r;
            float c0 = corr_s[m0], c1 = corr_s[m0 + 8];
#pragma unroll
            for (int j = 0; j < 2; j++) {
                oacc[i][j][0] *= c0; oacc[i][j][1] *= c0;
                oacc[i][j][2] *= c1; oacc[i][j][3] *= c1;
            }
        }
#pragma unroll
        for (int kk = 0; kk < 8; kk++) {
            unsigned a[2][4], b[2][2];
#pragma unroll
            for (int i = 0; i < 2; i++) {
                int m0 = wm * 32 + i * 16;
                a[i][0] = Su[(m0 + r) * AST + kk * 8 + c];
                a[i][1] = Su[(m0 + r + 8) * AST + kk * 8 + c];
                a[i][2] = Su[(m0 + r) * AST + kk * 8 + c + 4];
                a[i][3] = Su[(m0 + r + 8) * AST + kk * 8 + c + 4];
            }
#pragma unroll
            for (int j = 0; j < 2; j++) {
                int n0 = wn * 16 + j * 8 + r;
                b[j][0] = Vs[(kk * 8 + c) * VST + n0];
                b[j][1] = Vs[(kk * 8 + c + 4) * VST + n0];
            }
#pragma unroll
            for (int i = 0; i < 2; i++)
#pragma unroll
                for (int j = 0; j < 2; j++)
                    mma8(oacc[i][j], a[i], b[j]);
        }
    }

    const int b = bh >> 4, head = bh & 15;
#pragma unroll
    for (int i = 0; i < 2; i++) {
        int m0 = wm * 32 + i * 16 + r;
        float inv0 = 1.f / row_l[m0];
        float inv1 = 1.f / row_l[m0 + 8];
#pragma unroll
        for (int j = 0; j < 2; j++) {
            int n0 = wn * 16 + j * 8 + 2 * c;
            int col = head * 64 + n0;
            size_t q0 = (size_t)b * SS + mblk * 64 + m0;
            *(float2*)&g_Y[q0 * DD + col] =
                make_float2(oacc[i][j][0] * inv0, oacc[i][j][1] * inv0);
            *(float2*)&g_Y[(q0 + 8) * DD + col] =
                make_float2(oacc[i][j][2] * inv1, oacc[i][j][3] * inv1);
        }
    }
}

// ---------------------------------------------------------------------------
extern "C" void kernel_launch(void* const* d_in, const int* in_sizes, int n_in,
                              void* d_out, int out_size)
{
    const float* x      = (const float*)d_in[0];
    const float* W_attn = (const float*)d_in[1];
    const float* b_attn = (const float*)d_in[2];
    const float* W_out  = (const float*)d_in[3];
    const float* b_out  = (const float*)d_in[4];
    float* out = (float*)d_out;

    (void)in_sizes; (void)n_in; (void)out_size;

    dim3 thr(256);

    gemm_tc<0><<<dim3(3072 / 128, MROWS / 128), thr>>>(x, W_attn, b_attn, nullptr);

    size_t smem = (size_t)(3 * 64 * AST + 64 * VST) * 4 + 3 * 64 * 4;
    cudaFuncSetAttribute((const void*)attn_tc,
                         cudaFuncAttributeMaxDynamicSharedMemorySize, (int)smem);
    attn_tc<<<dim3(BB * HH, SS / 64), thr, smem>>>();

    gemm_tc<1><<<dim3(1024 / 128, MROWS / 128), thr>>>(nullptr, W_out, b_out, out);
}

// round 3
// speedup vs baseline: 3.1449x; 1.3892x over previous
#include <cuda_runtime.h>
#include <math.h>

#define BB 4
#define SS 2048
#define DD 1024
#define HH 16
#define HD 64
#define MROWS (BB * SS)   // 8192

// Scratch (allocation-free: __device__ globals)
__device__ float g_K[BB * HH * SS * HD];
__device__ float g_Q[BB * HH * SS * HD];
__device__ float g_V[BB * HH * SS * HD];
__device__ float g_Y[BB * SS * DD];
__device__ float g_xr[MROWS * DD];     // x rounded to tf32
__device__ float g_Wa[3 * DD * DD];    // W_attn rounded
__device__ float g_Wo[DD * DD];        // W_out rounded

// ---------------------------------------------------------------------------
// helpers
// ---------------------------------------------------------------------------
__device__ __forceinline__ unsigned f2t(float f) {
    unsigned u;
    asm("cvt.rna.tf32.f32 %0, %1;" : "=r"(u) : "f"(f));
    return u;
}

__device__ __forceinline__ void mma8(float* c, const unsigned* a, const unsigned* b) {
    asm volatile(
        "mma.sync.aligned.m16n8k8.row.col.f32.tf32.tf32.f32 "
        "{%0,%1,%2,%3}, {%4,%5,%6,%7}, {%8,%9}, {%0,%1,%2,%3};\n"
        : "+f"(c[0]), "+f"(c[1]), "+f"(c[2]), "+f"(c[3])
        : "r"(a[0]), "r"(a[1]), "r"(a[2]), "r"(a[3]), "r"(b[0]), "r"(b[1]));
}

__device__ __forceinline__ void cpa16(void* s, const void* g) {
    unsigned sa = (unsigned)__cvta_generic_to_shared(s);
    asm volatile("cp.async.cg.shared.global [%0], [%1], 16;\n"
                 :: "r"(sa), "l"(g) : "memory");
}
__device__ __forceinline__ void cp_commit() {
    asm volatile("cp.async.commit_group;\n" ::: "memory");
}
template <int N>
__device__ __forceinline__ void cp_wait() {
    asm volatile("cp.async.wait_group %0;\n" :: "n"(N) : "memory");
}

// ---------------------------------------------------------------------------
// Prep: round tensors to tf32-representable fp32 (TGT: 0=x, 1=W_attn, 2=W_out)
// ---------------------------------------------------------------------------
template <int TGT>
__global__ void round_tf32_k(const float* __restrict__ in, int n4) {
    float* outp = (TGT == 0) ? g_xr : (TGT == 1) ? g_Wa : g_Wo;
    int i = blockIdx.x * blockDim.x + threadIdx.x;
    if (i < n4) {
        float4 v = ((const float4*)in)[i];
        float4 o;
        o.x = __uint_as_float(f2t(v.x));
        o.y = __uint_as_float(f2t(v.y));
        o.z = __uint_as_float(f2t(v.z));
        o.w = __uint_as_float(f2t(v.w));
        ((float4*)outp)[i] = o;
    }
}

// ---------------------------------------------------------------------------
// TF32 GEMM, cp.async double-buffered. C[m,n]=sum_k A[m,k]*W[n,k]+bias[n]
// BLK 128x128x32, 256 thr (8 warps 4m x 2n), warp tile 32x64.
// EPI==0: A=g_xr, W=g_Wa, scatter rounded into g_K/g_Q/g_V (split k,q,v)
// EPI==1: A=g_Y,  W=g_Wo, plain fp32 store + bias
// Dynamic smem: 2 stages x (As 128x36 + Bs 128x36) floats = 73728 B
// ---------------------------------------------------------------------------
#define GST 36

template <int EPI>
__global__ __launch_bounds__(256) void gemm_tc(
    const float* __restrict__ bias, float* __restrict__ out)
{
    const float* A = (EPI == 0) ? (const float*)g_xr : (const float*)g_Y;
    const float* W = (EPI == 0) ? (const float*)g_Wa : (const float*)g_Wo;
    extern __shared__ float dsm[];
    float* Asm = dsm;                 // [2][128*GST]
    float* Bsm = dsm + 2 * 128 * GST; // [2][128*GST]

    const int t = threadIdx.x, lane = t & 31, warp = t >> 5;
    const int wm = warp & 3, wn = warp >> 2;
    const int r = lane >> 2, c = lane & 3;
    const int mBase = blockIdx.y * 128, nBase = blockIdx.x * 128;

    float acc[2][8][4];
#pragma unroll
    for (int i = 0; i < 2; i++)
#pragma unroll
        for (int j = 0; j < 8; j++)
#pragma unroll
            for (int q = 0; q < 4; q++) acc[i][j][q] = 0.f;

    // stage loader: 128 rows x 8 float4 per tensor
    auto load_stage = [&](int s, int k0) {
#pragma unroll
        for (int u0 = 0; u0 < 4; u0++) {
            int u = t + u0 * 256;
            int row = u >> 3, cg = u & 7;
            cpa16(&Asm[s * 128 * GST + row * GST + cg * 4],
                  &A[(size_t)(mBase + row) * 1024 + k0 + cg * 4]);
            cpa16(&Bsm[s * 128 * GST + row * GST + cg * 4],
                  &W[(size_t)(nBase + row) * 1024 + k0 + cg * 4]);
        }
        cp_commit();
    };

    load_stage(0, 0);

    for (int kt = 0; kt < 32; kt++) {
        int buf = kt & 1;
        if (kt < 31) {
            load_stage(buf ^ 1, (kt + 1) * 32);
            cp_wait<1>();
        } else {
            cp_wait<0>();
        }
        __syncthreads();

        const float* Ab = &Asm[buf * 128 * GST];
        const float* Bb = &Bsm[buf * 128 * GST];
#pragma unroll
        for (int kk = 0; kk < 4; kk++) {
            unsigned a[2][4], b[8][2];
#pragma unroll
            for (int i = 0; i < 2; i++) {
                int m0 = wm * 32 + i * 16;
                a[i][0] = __float_as_uint(Ab[(m0 + r) * GST + kk * 8 + c]);
                a[i][1] = __float_as_uint(Ab[(m0 + r + 8) * GST + kk * 8 + c]);
                a[i][2] = __float_as_uint(Ab[(m0 + r) * GST + kk * 8 + c + 4]);
                a[i][3] = __float_as_uint(Ab[(m0 + r + 8) * GST + kk * 8 + c + 4]);
            }
#pragma unroll
            for (int j = 0; j < 8; j++) {
                int n0 = wn * 64 + j * 8 + r;
                b[j][0] = __float_as_uint(Bb[n0 * GST + kk * 8 + c]);
                b[j][1] = __float_as_uint(Bb[n0 * GST + kk * 8 + c + 4]);
            }
#pragma unroll
            for (int i = 0; i < 2; i++)
#pragma unroll
                for (int j = 0; j < 8; j++)
                    mma8(acc[i][j], a[i], b[j]);
        }
        __syncthreads();
    }

#pragma unroll
    for (int i = 0; i < 2; i++) {
#pragma unroll
        for (int j = 0; j < 8; j++) {
            int mg0 = mBase + wm * 32 + i * 16 + r;
            int ng = nBase + wn * 64 + j * 8 + 2 * c;
            if (EPI == 0) {
#pragma unroll
                for (int h = 0; h < 2; h++) {
                    int m = mg0 + h * 8;
                    int bb = m >> 11, s = m & 2047;
#pragma unroll
                    for (int e = 0; e < 2; e++) {
                        int n = ng + e;
                        float v = acc[i][j][h * 2 + e] + bias[n];
                        int chunk = n >> 10;   // 0=k,1=q,2=v
                        int d = n & 1023;
                        int hh = d >> 6, hd = d & 63;
                        size_t idx = ((size_t)(bb * HH + hh) * SS + s) * HD + hd;
                        float vr = __uint_as_float(f2t(v));  // pre-round for next stage
                        if (chunk == 0)      g_K[idx] = vr;
                        else if (chunk == 1) g_Q[idx] = vr;
                        else                 g_V[idx] = vr;
                    }
                }
            } else {
                float2 bv = *(const float2*)&bias[ng];
                *(float2*)&out[(size_t)mg0 * DD + ng] =
                    make_float2(acc[i][j][0] + bv.x, acc[i][j][1] + bv.y);
                *(float2*)&out[(size_t)(mg0 + 8) * DD + ng] =
                    make_float2(acc[i][j][2] + bv.x, acc[i][j][3] + bv.y);
            }
        }
    }
}

// ---------------------------------------------------------------------------
// Flash attention, TF32 mma, cp.async double-buffered K/V.
// CTA tile: 128 q-rows x 64 k-cols. 256 thr (8 warps 4m x 2n), warp 32x32.
// Q/K/V are pre-rounded tf32 -> raw bits into mma. P rounded via f2t.
// Output written pre-permuted+rounded to g_Y [B,S,D].
// ---------------------------------------------------------------------------
#define AST 68
#define VST 72

__global__ __launch_bounds__(256) void attn_tc()
{
    extern __shared__ float dsa[];
    float* Qs   = dsa;                    // [128][AST]
    float* Su   = Qs + 128 * AST;         // [128][AST] scores / P
    float* Ks   = Su + 128 * AST;         // [2][64][AST]
    float* Vs   = Ks + 2 * 64 * AST;      // [2][64][VST]
    float* row_m  = Vs + 2 * 64 * VST;    // [128]
    float* row_l  = row_m + 128;
    float* corr_s = row_l + 128;

    const int t = threadIdx.x, lane = t & 31, warp = t >> 5;
    const int wm = warp & 3, wn = warp >> 2;
    const int r = lane >> 2, c = lane & 3;
    const int bh = blockIdx.x, mblk = blockIdx.y;

    const float* Qg  = g_Q + ((size_t)bh * SS + mblk * 128) * HD;
    const float* Kg0 = g_K + (size_t)bh * SS * HD;
    const float* Vg0 = g_V + (size_t)bh * SS * HD;

    auto load_kv = [&](int s, int jt) {
        const float* Kg = Kg0 + (size_t)jt * 64 * HD;
        const float* Vg = Vg0 + (size_t)jt * 64 * HD;
#pragma unroll
        for (int u0 = 0; u0 < 4; u0++) {
            int u = t + u0 * 256;
            int row = u >> 4, cg = u & 15;
            cpa16(&Ks[s * 64 * AST + row * AST + cg * 4], &Kg[row * 64 + cg * 4]);
            cpa16(&Vs[s * 64 * VST + row * VST + cg * 4], &Vg[row * 64 + cg * 4]);
        }
        cp_commit();
    };

    // group 0: K/V tile 0 + Q tile
    {
#pragma unroll
        for (int u0 = 0; u0 < 4; u0++) {
            int u = t + u0 * 256;
            int row = u >> 4, cg = u & 15;
            cpa16(&Ks[row * AST + cg * 4], &Kg0[row * 64 + cg * 4]);
            cpa16(&Vs[row * VST + cg * 4], &Vg0[row * 64 + cg * 4]);
        }
#pragma unroll
        for (int u0 = 0; u0 < 8; u0++) {
            int u = t + u0 * 256;
            int row = u >> 4, cg = u & 15;
            cpa16(&Qs[row * AST + cg * 4], &Qg[row * 64 + cg * 4]);
        }
        cp_commit();
    }
    if (t < 128) { row_m[t] = -1e30f; row_l[t] = 0.f; }

    float oacc[2][4][4];
#pragma unroll
    for (int i = 0; i < 2; i++)
#pragma unroll
        for (int j = 0; j < 4; j++)
#pragma unroll
            for (int q = 0; q < 4; q++) oacc[i][j][q] = 0.f;

    for (int jt = 0; jt < SS / 64; jt++) {
        int buf = jt & 1;
        if (jt < SS / 64 - 1) {
            load_kv(buf ^ 1, jt + 1);
            cp_wait<1>();
        } else {
            cp_wait<0>();
        }
        __syncthreads();   // (a) cur K/V + Q visible

        const float* Kb = &Ks[buf * 64 * AST];
        const float* Vb = &Vs[buf * 64 * VST];

        // --- scores S = Q @ K^T ---
        float sacc[2][4][4];
#pragma unroll
        for (int i = 0; i < 2; i++)
#pragma unroll
            for (int j = 0; j < 4; j++)
#pragma unroll
                for (int q = 0; q < 4; q++) sacc[i][j][q] = 0.f;

#pragma unroll
        for (int kk = 0; kk < 8; kk++) {
            unsigned a[2][4], b[4][2];
#pragma unroll
            for (int i = 0; i < 2; i++) {
                int m0 = wm * 32 + i * 16;
                a[i][0] = __float_as_uint(Qs[(m0 + r) * AST + kk * 8 + c]);
                a[i][1] = __float_as_uint(Qs[(m0 + r + 8) * AST + kk * 8 + c]);
                a[i][2] = __float_as_uint(Qs[(m0 + r) * AST + kk * 8 + c + 4]);
                a[i][3] = __float_as_uint(Qs[(m0 + r + 8) * AST + kk * 8 + c + 4]);
            }
#pragma unroll
            for (int j = 0; j < 4; j++) {
                int n0 = wn * 32 + j * 8 + r;
                b[j][0] = __float_as_uint(Kb[n0 * AST + kk * 8 + c]);
                b[j][1] = __float_as_uint(Kb[n0 * AST + kk * 8 + c + 4]);
            }
#pragma unroll
            for (int i = 0; i < 2; i++)
#pragma unroll
                for (int j = 0; j < 4; j++)
                    mma8(sacc[i][j], a[i], b[j]);
        }

        // store scaled scores
#pragma unroll
        for (int i = 0; i < 2; i++)
#pragma unroll
            for (int j = 0; j < 4; j++) {
                int m0 = wm * 32 + i * 16 + r;
                int n0 = wn * 32 + j * 8 + 2 * c;
                *(float2*)&Su[m0 * AST + n0] =
                    make_float2(sacc[i][j][0] * 0.125f, sacc[i][j][1] * 0.125f);
                *(float2*)&Su[(m0 + 8) * AST + n0] =
                    make_float2(sacc[i][j][2] * 0.125f, sacc[i][j][3] * 0.125f);
            }
        __syncthreads();   // (b)

        // --- online softmax: 2 threads per row, 32 cols each ---
        {
            int row = t >> 1, half = t & 1;
            float v[32];
#pragma unroll
            for (int ii = 0; ii < 8; ii++) {
                float4 f = *(const float4*)&Su[row * AST + half * 32 + ii * 4];
                v[ii * 4 + 0] = f.x; v[ii * 4 + 1] = f.y;
                v[ii * 4 + 2] = f.z; v[ii * 4 + 3] = f.w;
            }
            float mx = v[0];
#pragma unroll
            for (int e = 1; e < 32; e++) mx = fmaxf(mx, v[e]);
            mx = fmaxf(mx, __shfl_xor_sync(0xffffffffu, mx, 1));
            float old = row_m[row];
            float mnew = fmaxf(old, mx);
            float corr = __expf(old - mnew);
            float sum = 0.f;
            unsigned pv[32];
#pragma unroll
            for (int e = 0; e < 32; e++) {
                float p = __expf(v[e] - mnew);
                sum += p;
                pv[e] = f2t(p);
            }
            sum += __shfl_xor_sync(0xffffffffu, sum, 1);
#pragma unroll
            for (int ii = 0; ii < 8; ii++)
                *(uint4*)&((unsigned*)Su)[row * AST + half * 32 + ii * 4] =
                    make_uint4(pv[ii * 4], pv[ii * 4 + 1], pv[ii * 4 + 2], pv[ii * 4 + 3]);
            if (half == 0) {
                row_m[row] = mnew;
                row_l[row] = row_l[row] * corr + sum;
                corr_s[row] = corr;
            }
        }
        __syncthreads();   // (c)

        // --- rescale O, then O += P @ V ---
#pragma unroll
        for (int i = 0; i < 2; i++) {
            int m0 = wm * 32 + i * 16 + r;
            float c0 = corr_s[m0], c1 = corr_s[m0 + 8];
#pragma unroll
            for (int j = 0; j < 4; j++) {
                oacc[i][j][0] *= c0; oacc[i][j][1] *= c0;
                oacc[i][j][2] *= c1; oacc[i][j][3] *= c1;
            }
        }
#pragma unroll
        for (int kk = 0; kk < 8; kk++) {
            unsigned a[2][4], b[4][2];
#pragma unroll
            for (int i = 0; i < 2; i++) {
                int m0 = wm * 32 + i * 16;
                a[i][0] = __float_as_uint(Su[(m0 + r) * AST + kk * 8 + c]);
                a[i][1] = __float_as_uint(Su[(m0 + r + 8) * AST + kk * 8 + c]);
                a[i][2] = __float_as_uint(Su[(m0 + r) * AST + kk * 8 + c + 4]);
                a[i][3] = __float_as_uint(Su[(m0 + r + 8) * AST + kk * 8 + c + 4]);
            }
#pragma unroll
            for (int j = 0; j < 4; j++) {
                int n0 = wn * 32 + j * 8 + r;
                b[j][0] = __float_as_uint(Vb[(kk * 8 + c) * VST + n0]);
                b[j][1] = __float_as_uint(Vb[(kk * 8 + c + 4) * VST + n0]);
            }
#pragma unroll
            for (int i = 0; i < 2; i++)
#pragma unroll
                for (int j = 0; j < 4; j++)
                    mma8(oacc[i][j], a[i], b[j]);
        }
        __syncthreads();   // (d) protect buffers before next issue
    }

    // --- normalize + write rounded to g_Y [B,S,D] ---
    const int b = bh >> 4, head = bh & 15;
#pragma unroll
    for (int i = 0; i < 2; i++) {
        int m0 = wm * 32 + i * 16 + r;
        float inv0 = 1.f / row_l[m0];
        float inv1 = 1.f / row_l[m0 + 8];
#pragma unroll
        for (int j = 0; j < 4; j++) {
            int col = head * 64 + wn * 32 + j * 8 + 2 * c;
            size_t q0 = (size_t)b * SS + mblk * 128 + m0;
            *(float2*)&g_Y[q0 * DD + col] = make_float2(
                __uint_as_float(f2t(oacc[i][j][0] * inv0)),
                __uint_as_float(f2t(oacc[i][j][1] * inv0)));
            *(float2*)&g_Y[(q0 + 8) * DD + col] = make_float2(
                __uint_as_float(f2t(oacc[i][j][2] * inv1)),
                __uint_as_float(f2t(oacc[i][j][3] * inv1)));
        }
    }
}

// ---------------------------------------------------------------------------
extern "C" void kernel_launch(void* const* d_in, const int* in_sizes, int n_in,
                              void* d_out, int out_size)
{
    const float* x      = (const float*)d_in[0];
    const float* W_attn = (const float*)d_in[1];
    const float* b_attn = (const float*)d_in[2];
    const float* W_out  = (const float*)d_in[3];
    const float* b_out  = (const float*)d_in[4];
    float* out = (float*)d_out;

    (void)in_sizes; (void)n_in; (void)out_size;

    // 0) pre-round inputs to tf32 grid
    round_tf32_k<0><<<MROWS * DD / 4 / 256, 256>>>(x,      MROWS * DD / 4);
    round_tf32_k<1><<<3 * DD * DD / 4 / 256, 256>>>(W_attn, 3 * DD * DD / 4);
    round_tf32_k<2><<<DD * DD / 4 / 256, 256>>>(W_out,  DD * DD / 4);

    size_t gsm = (size_t)2 * 2 * 128 * GST * sizeof(float);   // 73728
    cudaFuncSetAttribute((const void*)gemm_tc<0>,
                         cudaFuncAttributeMaxDynamicSharedMemorySize, (int)gsm);
    cudaFuncSetAttribute((const void*)gemm_tc<1>,
                         cudaFuncAttributeMaxDynamicSharedMemorySize, (int)gsm);

    // 1) QKV projection -> rounded K/Q/V in [B,H,S,HD]
    gemm_tc<0><<<dim3(3072 / 128, MROWS / 128), 256, gsm>>>(b_attn, nullptr);

    // 2) flash attention -> rounded Y in [B,S,D]
    size_t asm_ = (size_t)(2 * 128 * AST + 2 * 64 * AST + 2 * 64 * VST + 3 * 128)
                  * sizeof(float);   // 142848
    cudaFuncSetAttribute((const void*)attn_tc,
                         cudaFuncAttributeMaxDynamicSharedMemorySize, (int)asm_);
    attn_tc<<<dim3(BB * HH, SS / 128), 256, asm_>>>();

    // 3) output projection (fp32 result)
    gemm_tc<1><<<dim3(1024 / 128, MROWS / 128), 256, gsm>>>(b_out, out);
}

// round 4
// speedup vs baseline: 3.6041x; 1.1460x over previous
#include <cuda_runtime.h>
#include <math.h>

#define BB 4
#define SS 2048
#define DD 1024
#define HH 16
#define HD 64
#define MROWS (BB * SS)   // 8192

// Scratch (allocation-free: __device__ globals)
__device__ float g_K[BB * HH * SS * HD];
__device__ float g_Q[BB * HH * SS * HD];
__device__ float g_V[BB * HH * SS * HD];
__device__ float g_Y[BB * SS * DD];
__device__ float g_xr[MROWS * DD];     // x rounded to tf32
__device__ float g_Wa[3 * DD * DD];    // W_attn rounded
__device__ float g_Wo[DD * DD];        // W_out rounded

// ---------------------------------------------------------------------------
// helpers
// ---------------------------------------------------------------------------
__device__ __forceinline__ unsigned f2t(float f) {
    unsigned u;
    asm("cvt.rna.tf32.f32 %0, %1;" : "=r"(u) : "f"(f));
    return u;
}

__device__ __forceinline__ void mma8(float* c, const unsigned* a, const unsigned* b) {
    asm volatile(
        "mma.sync.aligned.m16n8k8.row.col.f32.tf32.tf32.f32 "
        "{%0,%1,%2,%3}, {%4,%5,%6,%7}, {%8,%9}, {%0,%1,%2,%3};\n"
        : "+f"(c[0]), "+f"(c[1]), "+f"(c[2]), "+f"(c[3])
        : "r"(a[0]), "r"(a[1]), "r"(a[2]), "r"(a[3]), "r"(b[0]), "r"(b[1]));
}

__device__ __forceinline__ void cpa16(void* s, const void* g) {
    unsigned sa = (unsigned)__cvta_generic_to_shared(s);
    asm volatile("cp.async.cg.shared.global [%0], [%1], 16;\n"
                 :: "r"(sa), "l"(g) : "memory");
}
__device__ __forceinline__ void cp_commit() {
    asm volatile("cp.async.commit_group;\n" ::: "memory");
}
template <int N>
__device__ __forceinline__ void cp_wait() {
    asm volatile("cp.async.wait_group %0;\n" :: "n"(N) : "memory");
}

// ---------------------------------------------------------------------------
// Prep: round tensors to tf32-representable fp32 (TGT: 0=x, 1=W_attn, 2=W_out)
// ---------------------------------------------------------------------------
template <int TGT>
__global__ void round_tf32_k(const float* __restrict__ in, int n4) {
    float* outp = (TGT == 0) ? g_xr : (TGT == 1) ? g_Wa : g_Wo;
    int i = blockIdx.x * blockDim.x + threadIdx.x;
    if (i < n4) {
        float4 v = ((const float4*)in)[i];
        float4 o;
        o.x = __uint_as_float(f2t(v.x));
        o.y = __uint_as_float(f2t(v.y));
        o.z = __uint_as_float(f2t(v.z));
        o.w = __uint_as_float(f2t(v.w));
        ((float4*)outp)[i] = o;
    }
}

// ---------------------------------------------------------------------------
// TF32 GEMM, cp.async double-buffered (unchanged from round 3).
// ---------------------------------------------------------------------------
#define GST 36

template <int EPI>
__global__ __launch_bounds__(256) void gemm_tc(
    const float* __restrict__ bias, float* __restrict__ out)
{
    const float* A = (EPI == 0) ? (const float*)g_xr : (const float*)g_Y;
    const float* W = (EPI == 0) ? (const float*)g_Wa : (const float*)g_Wo;
    extern __shared__ float dsm[];
    float* Asm = dsm;
    float* Bsm = dsm + 2 * 128 * GST;

    const int t = threadIdx.x, lane = t & 31, warp = t >> 5;
    const int wm = warp & 3, wn = warp >> 2;
    const int r = lane >> 2, c = lane & 3;
    const int mBase = blockIdx.y * 128, nBase = blockIdx.x * 128;

    float acc[2][8][4];
#pragma unroll
    for (int i = 0; i < 2; i++)
#pragma unroll
        for (int j = 0; j < 8; j++)
#pragma unroll
            for (int q = 0; q < 4; q++) acc[i][j][q] = 0.f;

    auto load_stage = [&](int s, int k0) {
#pragma unroll
        for (int u0 = 0; u0 < 4; u0++) {
            int u = t + u0 * 256;
            int row = u >> 3, cg = u & 7;
            cpa16(&Asm[s * 128 * GST + row * GST + cg * 4],
                  &A[(size_t)(mBase + row) * 1024 + k0 + cg * 4]);
            cpa16(&Bsm[s * 128 * GST + row * GST + cg * 4],
                  &W[(size_t)(nBase + row) * 1024 + k0 + cg * 4]);
        }
        cp_commit();
    };

    load_stage(0, 0);

    for (int kt = 0; kt < 32; kt++) {
        int buf = kt & 1;
        if (kt < 31) {
            load_stage(buf ^ 1, (kt + 1) * 32);
            cp_wait<1>();
        } else {
            cp_wait<0>();
        }
        __syncthreads();

        const float* Ab = &Asm[buf * 128 * GST];
        const float* Bb = &Bsm[buf * 128 * GST];
#pragma unroll
        for (int kk = 0; kk < 4; kk++) {
            unsigned a[2][4], b[8][2];
#pragma unroll
            for (int i = 0; i < 2; i++) {
                int m0 = wm * 32 + i * 16;
                a[i][0] = __float_as_uint(Ab[(m0 + r) * GST + kk * 8 + c]);
                a[i][1] = __float_as_uint(Ab[(m0 + r + 8) * GST + kk * 8 + c]);
                a[i][2] = __float_as_uint(Ab[(m0 + r) * GST + kk * 8 + c + 4]);
                a[i][3] = __float_as_uint(Ab[(m0 + r + 8) * GST + kk * 8 + c + 4]);
            }
#pragma unroll
            for (int j = 0; j < 8; j++) {
                int n0 = wn * 64 + j * 8 + r;
                b[j][0] = __float_as_uint(Bb[n0 * GST + kk * 8 + c]);
                b[j][1] = __float_as_uint(Bb[n0 * GST + kk * 8 + c + 4]);
            }
#pragma unroll
            for (int i = 0; i < 2; i++)
#pragma unroll
                for (int j = 0; j < 8; j++)
                    mma8(acc[i][j], a[i], b[j]);
        }
        __syncthreads();
    }

#pragma unroll
    for (int i = 0; i < 2; i++) {
#pragma unroll
        for (int j = 0; j < 8; j++) {
            int mg0 = mBase + wm * 32 + i * 16 + r;
            int ng = nBase + wn * 64 + j * 8 + 2 * c;
            if (EPI == 0) {
#pragma unroll
                for (int h = 0; h < 2; h++) {
                    int m = mg0 + h * 8;
                    int bb = m >> 11, s = m & 2047;
#pragma unroll
                    for (int e = 0; e < 2; e++) {
                        int n = ng + e;
                        float v = acc[i][j][h * 2 + e] + bias[n];
                        int chunk = n >> 10;   // 0=k,1=q,2=v
                        int d = n & 1023;
                        int hh = d >> 6, hd = d & 63;
                        size_t idx = ((size_t)(bb * HH + hh) * SS + s) * HD + hd;
                        float vr = __uint_as_float(f2t(v));
                        if (chunk == 0)      g_K[idx] = vr;
                        else if (chunk == 1) g_Q[idx] = vr;
                        else                 g_V[idx] = vr;
                    }
                }
            } else {
                float2 bv = *(const float2*)&bias[ng];
                *(float2*)&out[(size_t)mg0 * DD + ng] =
                    make_float2(acc[i][j][0] + bv.x, acc[i][j][1] + bv.y);
                *(float2*)&out[(size_t)(mg0 + 8) * DD + ng] =
                    make_float2(acc[i][j][2] + bv.x, acc[i][j][3] + bv.y);
            }
        }
    }
}

// ---------------------------------------------------------------------------
// Flash attention v2: 128 threads, 4 warps, CTA tile 64 q x 64 kv.
// Warp tile 16 q-rows x 64. Q fragments in registers (pre-scaled by 1/8),
// softmax entirely in registers (quad shuffles), P in per-warp smem region
// (syncwarp only). 2 block barriers per iteration. 2 CTAs/SM.
// ---------------------------------------------------------------------------
#define AST 68   // K tile + P tile stride
#define VST 72   // V tile stride

__global__ __launch_bounds__(128) void attn_tc()
{
    extern __shared__ float dsa[];
    float* Ks = dsa;                      // [2][64][AST]
    float* Vs = Ks + 2 * 64 * AST;        // [2][64][VST]
    float* Ps = Vs + 2 * 64 * VST;        // [4][16][AST] per-warp

    const int t = threadIdx.x, lane = t & 31, w = t >> 5;
    const int r = lane >> 2, c = lane & 3;
    const int bh = blockIdx.x, mblk = blockIdx.y;

    const float* Qg  = g_Q + ((size_t)bh * SS + mblk * 64) * HD;
    const float* Kg0 = g_K + (size_t)bh * SS * HD;
    const float* Vg0 = g_V + (size_t)bh * SS * HD;

    float* Pw = Ps + w * 16 * AST;

    // Q fragments in registers, pre-scaled by 1/sqrt(64)=0.125 (exact on tf32)
    unsigned qa[8][4];
#pragma unroll
    for (int kk = 0; kk < 8; kk++) {
        qa[kk][0] = __float_as_uint(Qg[(w * 16 + r) * 64 + kk * 8 + c] * 0.125f);
        qa[kk][1] = __float_as_uint(Qg[(w * 16 + r + 8) * 64 + kk * 8 + c] * 0.125f);
        qa[kk][2] = __float_as_uint(Qg[(w * 16 + r) * 64 + kk * 8 + c + 4] * 0.125f);
        qa[kk][3] = __float_as_uint(Qg[(w * 16 + r + 8) * 64 + kk * 8 + c + 4] * 0.125f);
    }

    auto load_kv = [&](int s, int jt) {
        const float* Kg = Kg0 + (size_t)jt * 64 * HD;
        const float* Vg = Vg0 + (size_t)jt * 64 * HD;
#pragma unroll
        for (int u0 = 0; u0 < 8; u0++) {
            int u = t + u0 * 128;          // 0..1023
            int row = u >> 4, cg = u & 15;
            cpa16(&Ks[s * 64 * AST + row * AST + cg * 4], &Kg[row * 64 + cg * 4]);
            cpa16(&Vs[s * 64 * VST + row * VST + cg * 4], &Vg[row * 64 + cg * 4]);
        }
        cp_commit();
    };

    load_kv(0, 0);

    float oacc[8][4];
#pragma unroll
    for (int j = 0; j < 8; j++)
#pragma unroll
        for (int q = 0; q < 4; q++) oacc[j][q] = 0.f;
    float mi0 = -1e30f, mi1 = -1e30f, li0 = 0.f, li1 = 0.f;

    for (int jt = 0; jt < SS / 64; jt++) {
        int buf = jt & 1;
        if (jt < SS / 64 - 1) {
            load_kv(buf ^ 1, jt + 1);
            cp_wait<1>();
        } else {
            cp_wait<0>();
        }
        __syncthreads();   // K/V(buf) visible to all warps

        const float* Kb = &Ks[buf * 64 * AST];
        const float* Vb = &Vs[buf * 64 * VST];

        // --- scores S = (Q/8) @ K^T : warp tile 16 x 64 ---
        float s[8][4];
#pragma unroll
        for (int j = 0; j < 8; j++)
#pragma unroll
            for (int q = 0; q < 4; q++) s[j][q] = 0.f;

#pragma unroll
        for (int kk = 0; kk < 8; kk++) {
            unsigned b[8][2];
#pragma unroll
            for (int j = 0; j < 8; j++) {
                int n0 = j * 8 + r;
                b[j][0] = __float_as_uint(Kb[n0 * AST + kk * 8 + c]);
                b[j][1] = __float_as_uint(Kb[n0 * AST + kk * 8 + c + 4]);
            }
#pragma unroll
            for (int j = 0; j < 8; j++)
                mma8(s[j], qa[kk], b[j]);
        }

        // --- online softmax in registers ---
        // rows: m0 = w*16+r (elems 0,1), m1 = m0+8 (elems 2,3)
        float mx0 = -1e30f, mx1 = -1e30f;
#pragma unroll
        for (int j = 0; j < 8; j++) {
            mx0 = fmaxf(mx0, fmaxf(s[j][0], s[j][1]));
            mx1 = fmaxf(mx1, fmaxf(s[j][2], s[j][3]));
        }
        mx0 = fmaxf(mx0, __shfl_xor_sync(0xffffffffu, mx0, 1));
        mx0 = fmaxf(mx0, __shfl_xor_sync(0xffffffffu, mx0, 2));
        mx1 = fmaxf(mx1, __shfl_xor_sync(0xffffffffu, mx1, 1));
        mx1 = fmaxf(mx1, __shfl_xor_sync(0xffffffffu, mx1, 2));

        float mnew0 = fmaxf(mi0, mx0), mnew1 = fmaxf(mi1, mx1);
        float corr0 = __expf(mi0 - mnew0), corr1 = __expf(mi1 - mnew1);
        mi0 = mnew0; mi1 = mnew1;

        float sum0 = 0.f, sum1 = 0.f;
#pragma unroll
        for (int j = 0; j < 8; j++) {
            s[j][0] = __expf(s[j][0] - mnew0);
            s[j][1] = __expf(s[j][1] - mnew0);
            s[j][2] = __expf(s[j][2] - mnew1);
            s[j][3] = __expf(s[j][3] - mnew1);
            sum0 += s[j][0] + s[j][1];
            sum1 += s[j][2] + s[j][3];
        }
        sum0 += __shfl_xor_sync(0xffffffffu, sum0, 1);
        sum0 += __shfl_xor_sync(0xffffffffu, sum0, 2);
        sum1 += __shfl_xor_sync(0xffffffffu, sum1, 1);
        sum1 += __shfl_xor_sync(0xffffffffu, sum1, 2);
        li0 = li0 * corr0 + sum0;
        li1 = li1 * corr1 + sum1;

        // rescale O accumulators
#pragma unroll
        for (int j = 0; j < 8; j++) {
            oacc[j][0] *= corr0; oacc[j][1] *= corr0;
            oacc[j][2] *= corr1; oacc[j][3] *= corr1;
        }

        // --- P (tf32-rounded) to per-warp smem ---
#pragma unroll
        for (int j = 0; j < 8; j++) {
            *(float2*)&Pw[r * AST + j * 8 + 2 * c] = make_float2(
                __uint_as_float(f2t(s[j][0])), __uint_as_float(f2t(s[j][1])));
            *(float2*)&Pw[(r + 8) * AST + j * 8 + 2 * c] = make_float2(
                __uint_as_float(f2t(s[j][2])), __uint_as_float(f2t(s[j][3])));
        }
        __syncwarp();

        // --- O += P @ V ---
#pragma unroll
        for (int kk = 0; kk < 8; kk++) {
            unsigned a[4], b[8][2];
            a[0] = __float_as_uint(Pw[r * AST + kk * 8 + c]);
            a[1] = __float_as_uint(Pw[(r + 8) * AST + kk * 8 + c]);
            a[2] = __float_as_uint(Pw[r * AST + kk * 8 + c + 4]);
            a[3] = __float_as_uint(Pw[(r + 8) * AST + kk * 8 + c + 4]);
#pragma unroll
            for (int j = 0; j < 8; j++) {
                int n0 = j * 8 + r;
                b[j][0] = __float_as_uint(Vb[(kk * 8 + c) * VST + n0]);
                b[j][1] = __float_as_uint(Vb[(kk * 8 + c + 4) * VST + n0]);
            }
#pragma unroll
            for (int j = 0; j < 8; j++)
                mma8(oacc[j], a, b[j]);
        }
        __syncthreads();   // all warps done with buf before it is refilled
    }

    // --- normalize + write rounded to g_Y [B,S,D] ---
    const int b = bh >> 4, head = bh & 15;
    float inv0 = 1.f / li0, inv1 = 1.f / li1;
    size_t q0 = (size_t)b * SS + mblk * 64 + w * 16 + r;
#pragma unroll
    for (int j = 0; j < 8; j++) {
        int col = head * 64 + j * 8 + 2 * c;
        *(float2*)&g_Y[q0 * DD + col] = make_float2(
            __uint_as_float(f2t(oacc[j][0] * inv0)),
            __uint_as_float(f2t(oacc[j][1] * inv0)));
        *(float2*)&g_Y[(q0 + 8) * DD + col] = make_float2(
            __uint_as_float(f2t(oacc[j][2] * inv1)),
            __uint_as_float(f2t(oacc[j][3] * inv1)));
    }
}

// ---------------------------------------------------------------------------
extern "C" void kernel_launch(void* const* d_in, const int* in_sizes, int n_in,
                              void* d_out, int out_size)
{
    const float* x      = (const float*)d_in[0];
    const float* W_attn = (const float*)d_in[1];
    const float* b_attn = (const float*)d_in[2];
    const float* W_out  = (const float*)d_in[3];
    const float* b_out  = (const float*)d_in[4];
    float* out = (float*)d_out;

    (void)in_sizes; (void)n_in; (void)out_size;

    // 0) pre-round inputs to tf32 grid
    round_tf32_k<0><<<MROWS * DD / 4 / 256, 256>>>(x,      MROWS * DD / 4);
    round_tf32_k<1><<<3 * DD * DD / 4 / 256, 256>>>(W_attn, 3 * DD * DD / 4);
    round_tf32_k<2><<<DD * DD / 4 / 256, 256>>>(W_out,  DD * DD / 4);

    size_t gsm = (size_t)2 * 2 * 128 * GST * sizeof(float);   // 73728
    cudaFuncSetAttribute((const void*)gemm_tc<0>,
                         cudaFuncAttributeMaxDynamicSharedMemorySize, (int)gsm);
    cudaFuncSetAttribute((const void*)gemm_tc<1>,
                         cudaFuncAttributeMaxDynamicSharedMemorySize, (int)gsm);

    // 1) QKV projection -> rounded K/Q/V in [B,H,S,HD]
    gemm_tc<0><<<dim3(3072 / 128, MROWS / 128), 256, gsm>>>(b_attn, nullptr);

    // 2) flash attention v2 -> rounded Y in [B,S,D]
    size_t asm_ = (size_t)(2 * 64 * AST + 2 * 64 * VST + 4 * 16 * AST)
                  * sizeof(float);   // 89088
    cudaFuncSetAttribute((const void*)attn_tc,
                         cudaFuncAttributeMaxDynamicSharedMemorySize, (int)asm_);
    attn_tc<<<dim3(BB * HH, SS / 64), 128, asm_>>>();

    // 3) output projection (fp32 result)
    gemm_tc<1><<<dim3(1024 / 128, MROWS / 128), 256, gsm>>>(b_out, out);
}